// round 12
// baseline (speedup 1.0000x reference)
#include <cuda_runtime.h>
#include <cuda_fp16.h>
#include <cstdint>
#include <math.h>

#define NTOK 8192
#define CDIM 1024
#define CR   256
#define NADP 10
#define HWSZ 4096
#define BBAT 2
#define NANCH 3

// ---------------- scratch ----------------
static __device__ __half g_norm[(long)NTOK * CDIM];
static __device__ __half g_w1t[(long)NADP * CR * CDIM];
static __device__ __half g_w2t[(long)NADP * CDIM * CR];
static __device__ float  g_bias1[NADP * CR];
static __device__ __half g_h[(long)NADP * NTOK * CR];
static __device__ float  g_accum[(long)NTOK * CDIM];
static __device__ int    g_cnt[NADP];
static __device__ int    g_toklist[NADP * NTOK];
static __device__ float  g_wt[NADP * NTOK];

// ---------------- helpers ----------------
__device__ __forceinline__ void mma_f16(float* d, uint32_t a0, uint32_t a1, uint32_t a2, uint32_t a3,
                                        uint32_t b0, uint32_t b1) {
    asm volatile("mma.sync.aligned.m16n8k16.row.col.f32.f16.f16.f32 "
        "{%0,%1,%2,%3}, {%4,%5,%6,%7}, {%8,%9}, {%0,%1,%2,%3};"
        : "+f"(d[0]), "+f"(d[1]), "+f"(d[2]), "+f"(d[3])
        : "r"(a0), "r"(a1), "r"(a2), "r"(a3), "r"(b0), "r"(b1));
}
__device__ __forceinline__ void cp16(uint32_t dst, const void* src) {
    asm volatile("cp.async.cg.shared.global [%0], [%1], 16;" :: "r"(dst), "l"(src));
}
#define CP_COMMIT() asm volatile("cp.async.commit_group;" ::: "memory")
#define CP_WAIT(n)  asm volatile("cp.async.wait_group %0;" :: "n"(n) : "memory")
__device__ __forceinline__ uint32_t smem_u32(const void* p) {
    uint32_t a;
    asm("{ .reg .u64 t; cvta.to.shared.u64 t, %1; cvt.u32.u64 %0, t; }" : "=r"(a) : "l"(p));
    return a;
}
__device__ __forceinline__ float gelu_exact(float x) {
    return 0.5f * x * (1.0f + erff(x * 0.70710678118654752440f));
}
__device__ __forceinline__ int adapter_idx(float v) {
    int idx = 0;
    idx += v > (1.0f / 9.0f);
    idx += v > (1.0f / 7.0f);
    idx += v > (1.0f / 5.0f);
    idx += v > (1.0f / 3.0f);
    idx += v > 1.0f;
    idx += v > 3.0f;
    idx += v > 5.0f;
    idx += v > 7.0f;
    idx += v > 9.0f;
    return idx;
}
__device__ __forceinline__ uint32_t lds_u32(const char* base, int row, int ch, int c) {
    return *(const uint32_t*)(base + row * 64 + ((ch ^ ((row >> 1) & 3)) << 4) + c * 4);
}

// ---------------- compaction (+ per-slot weights) ----------------
__global__ void compact_kernel(const float* __restrict__ ar) {
    int tok = blockIdx.x * 256 + threadIdx.x;
    if (tok >= NTOK) return;
    int b = tok >> 12, p = tok & (HWSZ - 1);
    int ids[NANCH];
#pragma unroll
    for (int na = 0; na < NANCH; na++)
        ids[na] = adapter_idx(ar[(long)(b * NANCH + na) * HWSZ + p]);
#pragma unroll
    for (int na = 0; na < NANCH; na++) {
        bool dup = false;
#pragma unroll
        for (int j = 0; j < NANCH; j++) if (j < na) dup |= (ids[j] == ids[na]);
        if (!dup) {
            int occ = 0;
#pragma unroll
            for (int j = 0; j < NANCH; j++) occ += (ids[j] == ids[na]);
            int a = ids[na];
            int s = atomicAdd(&g_cnt[a], 1);
            g_toklist[a * NTOK + s] = tok;
            g_wt[a * NTOK + s] = (float)occ * (1.0f / 3.0f);
        }
    }
}

// ---------------- weight prep (w1 scale-fold + transpose + bias1 fold) ----------------
__global__ void prep_w1_kernel(const float* __restrict__ ln_scale,
                               const float* __restrict__ ln_bias,
                               const float* __restrict__ w1) {
    __shared__ float t[32][33];
    __shared__ float bsum[8][33];
    int a = blockIdx.z, c0 = blockIdx.x * 32, d0 = blockIdx.y * 32;
    int tx = threadIdx.x, ty = threadIdx.y;
    float partial = 0.f;
#pragma unroll
    for (int jj = 0; jj < 4; jj++) {
        int ci = ty + jj * 8;
        float raw = w1[((long)a * CDIM + c0 + ci) * CR + d0 + tx];
        t[ci][tx] = raw * ln_scale[a * CDIM + c0 + ci];
        partial = fmaf(ln_bias[a * CDIM + c0 + ci], raw, partial);
    }
    bsum[ty][tx] = partial;
    __syncthreads();
#pragma unroll
    for (int jj = 0; jj < 4; jj++) {
        int di = ty + jj * 8;
        g_w1t[((long)a * CR + d0 + di) * CDIM + c0 + tx] = __float2half_rn(t[tx][di]);
    }
    if (ty == 0) {
        float s = 0.f;
#pragma unroll
        for (int j = 0; j < 8; j++) s += bsum[j][tx];
        atomicAdd(&g_bias1[a * CR + d0 + tx], s);
    }
}
__global__ void prep_w2_kernel(const float* __restrict__ w2) {
    __shared__ float t[32][33];
    int a = blockIdx.z, n0 = blockIdx.x * 32, k0 = blockIdx.y * 32;
    int tx = threadIdx.x, ty = threadIdx.y;
#pragma unroll
    for (int jj = 0; jj < 4; jj++) {
        int ki = ty + jj * 8;
        t[ki][tx] = w2[((long)a * CR + k0 + ki) * CDIM + n0 + tx];
    }
    __syncthreads();
#pragma unroll
    for (int jj = 0; jj < 4; jj++) {
        int ni = ty + jj * 8;
        g_w2t[((long)a * CDIM + n0 + ni) * CR + k0 + tx] = __float2half_rn(t[tx][ni]);
    }
}

// ---------------- fused LayerNorm: single feat read, smem-cached tile ----------------
// grid (HWSZ/32, B), block (32,8), dynamic smem = 1024*33*4 = 135168 B.
__global__ void ln_fused_kernel(const float* __restrict__ feat) {
    extern __shared__ float xs[];                 // [c][px], row stride 33
    __shared__ float ss[8][33], qq[8][33];
    __shared__ float sm_mean[32], sm_rstd[32];
    int b  = blockIdx.y;
    int p0 = blockIdx.x * 32;
    int tx = threadIdx.x, ty = threadIdx.y;
    const float* base = feat + (long)b * CDIM * HWSZ + p0;
    float s = 0.f, sq = 0.f;
#pragma unroll 8
    for (int c = ty; c < CDIM; c += 8) {
        float v = base[(long)c * HWSZ + tx];
        xs[c * 33 + tx] = v;
        s += v; sq = fmaf(v, v, sq);
    }
    ss[ty][tx] = s; qq[ty][tx] = sq;
    __syncthreads();
    if (ty == 0) {
        float S = 0.f, Q = 0.f;
#pragma unroll
        for (int j = 0; j < 8; j++) { S += ss[j][tx]; Q += qq[j][tx]; }
        float mean = S * (1.0f / CDIM);
        float var  = Q * (1.0f / CDIM) - mean * mean;
        sm_mean[tx] = mean;
        sm_rstd[tx] = rsqrtf(var + 1e-5f);
    }
    __syncthreads();
    // write: warp ty handles pixels ty, ty+8, ty+16, ty+24; lanes = consecutive c
#pragma unroll
    for (int pg = 0; pg < 4; pg++) {
        int pi = ty + pg * 8;
        long tok = (long)b * HWSZ + p0 + pi;
        float mean = sm_mean[pi], rstd = sm_rstd[pi];
        __half* dst = g_norm + tok * CDIM;
#pragma unroll 8
        for (int cc = 0; cc < 32; cc++) {
            int c = tx + cc * 32;
            dst[c] = __float2half_rn((xs[c * 33 + pi] - mean) * rstd);
        }
    }
}

// ---------------- fp16 mma.sync GEMM: 128x128 CTA, 4 warps of 64x64, cp.async 3-stage ----------------
#define G_STAGES   3
#define G_STAGE_B  16384
#define G_PTRS_B   2048
#define G_SMEM_TOTAL (G_PTRS_B + G_STAGES * G_STAGE_B)

__global__ void __launch_bounds__(128, 2)
mma_gemm(const __half* __restrict__ Ab, const __half* __restrict__ Bb,
         const float* __restrict__ bias, __half* __restrict__ Cb,
         const int* __restrict__ tlA,
         const int* __restrict__ tlE,
         const float* __restrict__ wts,
         float* __restrict__ accumC,
         int K, int lda, int ldb, int ldc,
         long sA, long sB, long sC, int mode)
{
    extern __shared__ char smem[];
    int tid = threadIdx.x;
    int mB = blockIdx.x * 128, nB = blockIdx.y * 128, a = blockIdx.z;

    int cnt = g_cnt[a];
    if (mB >= cnt) return;

    const __half* A = Ab + (long)a * sA;
    const __half* B = Bb + (long)a * sB;
    __half* C = Cb + (long)a * sC;
    const int* tla = tlA ? tlA + a * NTOK : nullptr;

    const __half** sAp = (const __half**)smem;
    const __half** sBp = sAp + 128;
    uint32_t sm_base = smem_u32(smem) + G_PTRS_B;

    {
        int m = mB + tid;
        int mc = m < cnt ? m : (cnt - 1);
        long arow = tla ? (long)tla[mc] : (long)mc;
        sAp[tid] = A + arow * lda;
        sBp[tid] = B + (long)(nB + tid) * ldb;
    }
    __syncthreads();

    int lane = tid & 31, wid = tid >> 5;
    int wm0 = (wid & 1) * 64;
    int wn0 = (wid >> 1) * 64;
    int r = lane >> 2, c = lane & 3;

    int nkt = K >> 5;
    int kc = tid & 3;
    int r0 = tid >> 2;

#define FILL_STAGE(sidx, k0)  do {                                             \
        uint32_t base = sm_base + (sidx) * G_STAGE_B;                          \
        _Pragma("unroll")                                                      \
        for (int i = 0; i < 4; i++) {                                          \
            int row = r0 + i * 32;                                             \
            uint32_t off = (uint32_t)(row * 64 + ((kc ^ ((row >> 1) & 3)) << 4)); \
            cp16(base + off, sAp[row] + (k0) + kc * 8);                        \
            cp16(base + 8192 + off, sBp[row] + (k0) + kc * 8);                 \
        }                                                                      \
        CP_COMMIT();                                                           \
    } while (0)

    float acc[4][8][4];
#pragma unroll
    for (int t = 0; t < 4; t++)
#pragma unroll
        for (int u = 0; u < 8; u++)
#pragma unroll
            for (int e = 0; e < 4; e++) acc[t][u][e] = 0.f;

    FILL_STAGE(0, 0);
    FILL_STAGE(1, 32);
    CP_WAIT(1);
    __syncthreads();

    for (int kt = 0; kt < nkt; kt++) {
        const char* As = smem + G_PTRS_B + (kt % 3) * G_STAGE_B;
        const char* Bs = As + 8192;

#pragma unroll
        for (int j = 0; j < 2; j++) {
            uint32_t bf[8][2];
#pragma unroll
            for (int u = 0; u < 8; u++) {
                int n = wn0 + u * 8 + r;
                bf[u][0] = lds_u32(Bs, n, 2 * j,     c);
                bf[u][1] = lds_u32(Bs, n, 2 * j + 1, c);
            }
#pragma unroll
            for (int t = 0; t < 4; t++) {
                int m0 = wm0 + t * 16 + r;
                uint32_t a0 = lds_u32(As, m0,     2 * j,     c);
                uint32_t a1 = lds_u32(As, m0 + 8, 2 * j,     c);
                uint32_t a2 = lds_u32(As, m0,     2 * j + 1, c);
                uint32_t a3 = lds_u32(As, m0 + 8, 2 * j + 1, c);
#pragma unroll
                for (int u = 0; u < 8; u++)
                    mma_f16(acc[t][u], a0, a1, a2, a3, bf[u][0], bf[u][1]);
            }
        }

        if (kt + 2 < nkt) {
            __syncthreads();
            FILL_STAGE((kt + 2) % 3, (kt + 2) * 32);
            CP_WAIT(1);
            __syncthreads();
        } else if (kt + 1 < nkt) {
            CP_WAIT(0);
            __syncthreads();
        }
    }

    // ---- epilogue ----
    if (mode == 2) {
        const int* tle = tlE + a * NTOK;
        const float* wta = wts + a * NTOK;
#pragma unroll
        for (int t = 0; t < 4; t++) {
            int gr0 = mB + wm0 + t * 16 + r;
            int gr1 = gr0 + 8;
            bool k0 = gr0 < cnt;
            bool k1 = gr1 < cnt;
            if (!k0 && !k1) continue;
            long t0 = k0 ? (long)tle[gr0] : 0;
            long t1 = k1 ? (long)tle[gr1] : 0;
            float w0 = k0 ? wta[gr0] : 0.f;
            float w1v = k1 ? wta[gr1] : 0.f;
            float* d0 = accumC + t0 * CDIM;
            float* d1 = accumC + t1 * CDIM;
#pragma unroll
            for (int u = 0; u < 8; u++) {
                int col = nB + wn0 + u * 8 + c * 2;
                if (k0) {
                    atomicAdd(d0 + col,     acc[t][u][0] * w0);
                    atomicAdd(d0 + col + 1, acc[t][u][1] * w0);
                }
                if (k1) {
                    atomicAdd(d1 + col,     acc[t][u][2] * w1v);
                    atomicAdd(d1 + col + 1, acc[t][u][3] * w1v);
                }
            }
        }
    } else {
#pragma unroll
        for (int t = 0; t < 4; t++) {
            int gr0 = mB + wm0 + t * 16 + r;
            int gr1 = gr0 + 8;
            bool k0 = gr0 < cnt;
            bool k1 = gr1 < cnt;
            if (!k0 && !k1) continue;
#pragma unroll
            for (int u = 0; u < 8; u++) {
                int col = nB + wn0 + u * 8 + c * 2;
                float b0v = bias[a * CR + col], b1v = bias[a * CR + col + 1];
                float v00 = gelu_exact(acc[t][u][0] + b0v);
                float v01 = gelu_exact(acc[t][u][1] + b1v);
                float v10 = gelu_exact(acc[t][u][2] + b0v);
                float v11 = gelu_exact(acc[t][u][3] + b1v);
                if (k0) *(__half2*)(C + (long)gr0 * ldc + col) =
                    __halves2half2(__float2half_rn(v00), __float2half_rn(v01));
                if (k1) *(__half2*)(C + (long)gr1 * ldc + col) =
                    __halves2half2(__float2half_rn(v10), __float2half_rn(v11));
            }
        }
    }
#undef FILL_STAGE
}

// ---------------- final: out = accum + feat, NCHW ----------------
__global__ void final_kernel(const float* __restrict__ feat, float* __restrict__ out) {
    __shared__ float t[32][33];
    int b  = blockIdx.z;
    int c0 = blockIdx.y * 32;
    int p0 = blockIdx.x * 32;
    int tx = threadIdx.x, ty = threadIdx.y;
#pragma unroll
    for (int pj = 0; pj < 4; pj++) {
        int pi = ty + pj * 8;
        long tok = (long)b * HWSZ + p0 + pi;
        t[pi][tx] = g_accum[tok * CDIM + c0 + tx];
    }
    __syncthreads();
    int tid = ty * 32 + tx;
    int pi  = tid & 31;
    int ci0 = tid >> 5;
#pragma unroll
    for (int cj = 0; cj < 4; cj++) {
        int ci = ci0 + cj * 8;
        long off = (long)(b * CDIM + c0 + ci) * HWSZ + p0 + pi;
        out[off] = t[pi][ci] + feat[off];
    }
}

// ---------------- launch ----------------
extern "C" void kernel_launch(void* const* d_in, const int* in_sizes, int n_in,
                              void* d_out, int out_size) {
    const float* feat     = (const float*)d_in[0];
    const float* ar       = (const float*)d_in[1];
    const float* ln_scale = (const float*)d_in[2];
    const float* ln_bias  = (const float*)d_in[3];
    const float* w1       = (const float*)d_in[4];
    const float* w2       = (const float*)d_in[5];
    float* out = (float*)d_out;

    __half *norm, *w1t, *w2t, *h;
    float *bias1, *accum, *wt;
    int *toklist, *cntp;
    cudaGetSymbolAddress((void**)&norm,    g_norm);
    cudaGetSymbolAddress((void**)&w1t,     g_w1t);
    cudaGetSymbolAddress((void**)&w2t,     g_w2t);
    cudaGetSymbolAddress((void**)&bias1,   g_bias1);
    cudaGetSymbolAddress((void**)&h,       g_h);
    cudaGetSymbolAddress((void**)&accum,   g_accum);
    cudaGetSymbolAddress((void**)&toklist, g_toklist);
    cudaGetSymbolAddress((void**)&wt,      g_wt);
    cudaGetSymbolAddress((void**)&cntp,    g_cnt);

    static bool attr_set = false;
    if (!attr_set) {
        cudaFuncSetAttribute(mma_gemm, cudaFuncAttributeMaxDynamicSharedMemorySize, G_SMEM_TOTAL);
        cudaFuncSetAttribute(ln_fused_kernel, cudaFuncAttributeMaxDynamicSharedMemorySize, 1024 * 33 * 4);
        attr_set = true;
    }

    cudaMemsetAsync(accum, 0, (long)NTOK * CDIM * sizeof(float));
    cudaMemsetAsync(cntp,  0, NADP * sizeof(int));
    cudaMemsetAsync(bias1, 0, NADP * CR * sizeof(float));

    compact_kernel<<<NTOK / 256, 256>>>(ar);
    prep_w1_kernel<<<dim3(CDIM / 32, CR / 32, NADP), dim3(32, 8)>>>(ln_scale, ln_bias, w1);
    prep_w2_kernel<<<dim3(CDIM / 32, CR / 32, NADP), dim3(32, 8)>>>(w2);
    ln_fused_kernel<<<dim3(HWSZ / 32, BBAT), dim3(32, 8), 1024 * 33 * 4>>>(feat);

    // GEMM1 (mode 1): h[a][slot] = gelu(norm[tok(slot)] @ w1t[a]^T + bias1[a])
    mma_gemm<<<dim3(NTOK / 128, CR / 128, NADP), 128, G_SMEM_TOTAL>>>(
        norm, w1t, bias1, h, toklist, nullptr, nullptr, nullptr,
        CDIM, CDIM, CDIM, CR,
        0L, (long)CR * CDIM, (long)NTOK * CR, 1);

    // GEMM2 (mode 2): accum[tok] += w * (h[a][slot] @ w2t[a]^T)
    mma_gemm<<<dim3(NTOK / 128, CDIM / 128, NADP), 128, G_SMEM_TOTAL>>>(
        h, w2t, nullptr, nullptr, nullptr, toklist, wt, accum,
        CR, CR, CR, CDIM,
        (long)NTOK * CR, (long)CDIM * CR, 0L, 2);

    // final: out = accum + feat (NCHW)
    final_kernel<<<dim3(HWSZ / 32, CDIM / 32, BBAT), dim3(32, 8)>>>(feat, out);
}

// round 13
// speedup vs baseline: 1.0242x; 1.0242x over previous
#include <cuda_runtime.h>
#include <cuda_fp16.h>
#include <cstdint>
#include <math.h>

#define NTOK 8192
#define CDIM 1024
#define CR   256
#define NADP 10
#define HWSZ 4096
#define BBAT 2
#define NANCH 3

// ---------------- scratch ----------------
static __device__ __half g_norm[(long)NTOK * CDIM];
static __device__ __half g_w1t[(long)NADP * CR * CDIM];
static __device__ __half g_w2t[(long)NADP * CDIM * CR];
static __device__ float  g_bias1[NADP * CR];
static __device__ __half g_h[(long)NADP * NTOK * CR];
static __device__ float  g_accum[(long)NTOK * CDIM];
static __device__ int    g_cnt[NADP];
static __device__ int    g_toklist[NADP * NTOK];
static __device__ float  g_wt[NADP * NTOK];
static __device__ float  g_mean[NTOK];
static __device__ float  g_rstd[NTOK];

// ---------------- helpers ----------------
__device__ __forceinline__ void mma_f16(float* d, uint32_t a0, uint32_t a1, uint32_t a2, uint32_t a3,
                                        uint32_t b0, uint32_t b1) {
    asm volatile("mma.sync.aligned.m16n8k16.row.col.f32.f16.f16.f32 "
        "{%0,%1,%2,%3}, {%4,%5,%6,%7}, {%8,%9}, {%0,%1,%2,%3};"
        : "+f"(d[0]), "+f"(d[1]), "+f"(d[2]), "+f"(d[3])
        : "r"(a0), "r"(a1), "r"(a2), "r"(a3), "r"(b0), "r"(b1));
}
__device__ __forceinline__ void cp16(uint32_t dst, const void* src) {
    asm volatile("cp.async.cg.shared.global [%0], [%1], 16;" :: "r"(dst), "l"(src));
}
#define CP_COMMIT() asm volatile("cp.async.commit_group;" ::: "memory")
#define CP_WAIT(n)  asm volatile("cp.async.wait_group %0;" :: "n"(n) : "memory")
__device__ __forceinline__ uint32_t smem_u32(const void* p) {
    uint32_t a;
    asm("{ .reg .u64 t; cvta.to.shared.u64 t, %1; cvt.u32.u64 %0, t; }" : "=r"(a) : "l"(p));
    return a;
}
__device__ __forceinline__ float gelu_exact(float x) {
    return 0.5f * x * (1.0f + erff(x * 0.70710678118654752440f));
}
__device__ __forceinline__ int adapter_idx(float v) {
    int idx = 0;
    idx += v > (1.0f / 9.0f);
    idx += v > (1.0f / 7.0f);
    idx += v > (1.0f / 5.0f);
    idx += v > (1.0f / 3.0f);
    idx += v > 1.0f;
    idx += v > 3.0f;
    idx += v > 5.0f;
    idx += v > 7.0f;
    idx += v > 9.0f;
    return idx;
}
__device__ __forceinline__ uint32_t lds_u32(const char* base, int row, int ch, int c) {
    return *(const uint32_t*)(base + row * 64 + ((ch ^ ((row >> 1) & 3)) << 4) + c * 4);
}

// ---------------- compaction (+ per-slot weights) ----------------
__global__ void compact_kernel(const float* __restrict__ ar) {
    int tok = blockIdx.x * 256 + threadIdx.x;
    if (tok >= NTOK) return;
    int b = tok >> 12, p = tok & (HWSZ - 1);
    int ids[NANCH];
#pragma unroll
    for (int na = 0; na < NANCH; na++)
        ids[na] = adapter_idx(ar[(long)(b * NANCH + na) * HWSZ + p]);
#pragma unroll
    for (int na = 0; na < NANCH; na++) {
        bool dup = false;
#pragma unroll
        for (int j = 0; j < NANCH; j++) if (j < na) dup |= (ids[j] == ids[na]);
        if (!dup) {
            int occ = 0;
#pragma unroll
            for (int j = 0; j < NANCH; j++) occ += (ids[j] == ids[na]);
            int a = ids[na];
            int s = atomicAdd(&g_cnt[a], 1);
            g_toklist[a * NTOK + s] = tok;
            g_wt[a * NTOK + s] = (float)occ * (1.0f / 3.0f);
        }
    }
}

// ---------------- weight prep (w1 scale-fold + transpose + bias1 fold) ----------------
__global__ void prep_w1_kernel(const float* __restrict__ ln_scale,
                               const float* __restrict__ ln_bias,
                               const float* __restrict__ w1) {
    __shared__ float t[32][33];
    __shared__ float bsum[8][33];
    int a = blockIdx.z, c0 = blockIdx.x * 32, d0 = blockIdx.y * 32;
    int tx = threadIdx.x, ty = threadIdx.y;
    float partial = 0.f;
#pragma unroll
    for (int jj = 0; jj < 4; jj++) {
        int ci = ty + jj * 8;
        float raw = w1[((long)a * CDIM + c0 + ci) * CR + d0 + tx];
        t[ci][tx] = raw * ln_scale[a * CDIM + c0 + ci];
        partial = fmaf(ln_bias[a * CDIM + c0 + ci], raw, partial);
    }
    bsum[ty][tx] = partial;
    __syncthreads();
#pragma unroll
    for (int jj = 0; jj < 4; jj++) {
        int di = ty + jj * 8;
        g_w1t[((long)a * CR + d0 + di) * CDIM + c0 + tx] = __float2half_rn(t[tx][di]);
    }
    if (ty == 0) {
        float s = 0.f;
#pragma unroll
        for (int j = 0; j < 8; j++) s += bsum[j][tx];
        atomicAdd(&g_bias1[a * CR + d0 + tx], s);
    }
}
__global__ void prep_w2_kernel(const float* __restrict__ w2) {
    __shared__ float t[32][33];
    int a = blockIdx.z, n0 = blockIdx.x * 32, k0 = blockIdx.y * 32;
    int tx = threadIdx.x, ty = threadIdx.y;
#pragma unroll
    for (int jj = 0; jj < 4; jj++) {
        int ki = ty + jj * 8;
        t[ki][tx] = w2[((long)a * CR + k0 + ki) * CDIM + n0 + tx];
    }
    __syncthreads();
#pragma unroll
    for (int jj = 0; jj < 4; jj++) {
        int ni = ty + jj * 8;
        g_w2t[((long)a * CDIM + n0 + ni) * CR + k0 + tx] = __float2half_rn(t[tx][ni]);
    }
}

// ---------------- LayerNorm pass 1: per-token stats (coalesced, full-chip) ----------------
__global__ void ln_stats_kernel(const float* __restrict__ feat) {
    int b  = blockIdx.y;
    int p0 = blockIdx.x * 32;
    int tx = threadIdx.x, ty = threadIdx.y;
    const float* base = feat + (long)b * CDIM * HWSZ + p0 + tx;
    float s = 0.f, sq = 0.f;
#pragma unroll 16
    for (int c = ty; c < CDIM; c += 8) {
        float v = base[(long)c * HWSZ];
        s += v; sq = fmaf(v, v, sq);
    }
    __shared__ float ss[8][33], qq[8][33];
    ss[ty][tx] = s; qq[ty][tx] = sq;
    __syncthreads();
    if (ty == 0) {
        float S = 0.f, Q = 0.f;
#pragma unroll
        for (int j = 0; j < 8; j++) { S += ss[j][tx]; Q += qq[j][tx]; }
        float mean = S * (1.0f / CDIM);
        float var  = Q * (1.0f / CDIM) - mean * mean;
        int tok = b * HWSZ + p0 + tx;
        g_mean[tok] = mean;
        g_rstd[tok] = rsqrtf(var + 1e-5f);
    }
}

// ---------------- LayerNorm pass 2: normalize + transpose ----------------
__global__ void ln_apply_kernel(const float* __restrict__ feat) {
    __shared__ float t[32][33];
    int b  = blockIdx.z;
    int c0 = blockIdx.y * 32;
    int p0 = blockIdx.x * 32;
    int tx = threadIdx.x, ty = threadIdx.y;
#pragma unroll
    for (int cj = 0; cj < 4; cj++) {
        int ci = ty + cj * 8;
        t[ci][tx] = feat[((long)b * CDIM + c0 + ci) * HWSZ + p0 + tx];
    }
    __syncthreads();
#pragma unroll
    for (int pj = 0; pj < 4; pj++) {
        int pi = ty + pj * 8;
        int tok = b * HWSZ + p0 + pi;
        float mean = g_mean[tok], rstd = g_rstd[tok];
        g_norm[(long)tok * CDIM + c0 + tx] = __float2half_rn((t[tx][pi] - mean) * rstd);
    }
}

// ---------------- fp16 mma.sync GEMM: 128x128 CTA, 4 warps of 64x64, cp.async 3-stage ----------------
#define G_STAGES   3
#define G_STAGE_B  16384
#define G_PTRS_B   2048
#define G_SMEM_TOTAL (G_PTRS_B + G_STAGES * G_STAGE_B)

__global__ void __launch_bounds__(128, 2)
mma_gemm(const __half* __restrict__ Ab, const __half* __restrict__ Bb,
         const float* __restrict__ bias, __half* __restrict__ Cb,
         const int* __restrict__ tlA,
         const int* __restrict__ tlE,
         const float* __restrict__ wts,
         float* __restrict__ accumC,
         int K, int lda, int ldb, int ldc,
         long sA, long sB, long sC, int mode)
{
    extern __shared__ char smem[];
    int tid = threadIdx.x;
    int mB = blockIdx.x * 128, nB = blockIdx.y * 128, a = blockIdx.z;

    int cnt = g_cnt[a];
    if (mB >= cnt) return;

    const __half* A = Ab + (long)a * sA;
    const __half* B = Bb + (long)a * sB;
    __half* C = Cb + (long)a * sC;
    const int* tla = tlA ? tlA + a * NTOK : nullptr;

    const __half** sAp = (const __half**)smem;
    const __half** sBp = sAp + 128;
    uint32_t sm_base = smem_u32(smem) + G_PTRS_B;

    {
        int m = mB + tid;
        int mc = m < cnt ? m : (cnt - 1);
        long arow = tla ? (long)tla[mc] : (long)mc;
        sAp[tid] = A + arow * lda;
        sBp[tid] = B + (long)(nB + tid) * ldb;
    }
    __syncthreads();

    int lane = tid & 31, wid = tid >> 5;
    int wm0 = (wid & 1) * 64;
    int wn0 = (wid >> 1) * 64;
    int r = lane >> 2, c = lane & 3;

    int nkt = K >> 5;
    int kc = tid & 3;
    int r0 = tid >> 2;

#define FILL_STAGE(sidx, k0)  do {                                             \
        uint32_t base = sm_base + (sidx) * G_STAGE_B;                          \
        _Pragma("unroll")                                                      \
        for (int i = 0; i < 4; i++) {                                          \
            int row = r0 + i * 32;                                             \
            uint32_t off = (uint32_t)(row * 64 + ((kc ^ ((row >> 1) & 3)) << 4)); \
            cp16(base + off, sAp[row] + (k0) + kc * 8);                        \
            cp16(base + 8192 + off, sBp[row] + (k0) + kc * 8);                 \
        }                                                                      \
        CP_COMMIT();                                                           \
    } while (0)

    float acc[4][8][4];
#pragma unroll
    for (int t = 0; t < 4; t++)
#pragma unroll
        for (int u = 0; u < 8; u++)
#pragma unroll
            for (int e = 0; e < 4; e++) acc[t][u][e] = 0.f;

    FILL_STAGE(0, 0);
    FILL_STAGE(1, 32);
    CP_WAIT(1);
    __syncthreads();

    for (int kt = 0; kt < nkt; kt++) {
        const char* As = smem + G_PTRS_B + (kt % 3) * G_STAGE_B;
        const char* Bs = As + 8192;

#pragma unroll
        for (int j = 0; j < 2; j++) {
            uint32_t bf[8][2];
#pragma unroll
            for (int u = 0; u < 8; u++) {
                int n = wn0 + u * 8 + r;
                bf[u][0] = lds_u32(Bs, n, 2 * j,     c);
                bf[u][1] = lds_u32(Bs, n, 2 * j + 1, c);
            }
#pragma unroll
            for (int t = 0; t < 4; t++) {
                int m0 = wm0 + t * 16 + r;
                uint32_t a0 = lds_u32(As, m0,     2 * j,     c);
                uint32_t a1 = lds_u32(As, m0 + 8, 2 * j,     c);
                uint32_t a2 = lds_u32(As, m0,     2 * j + 1, c);
                uint32_t a3 = lds_u32(As, m0 + 8, 2 * j + 1, c);
#pragma unroll
                for (int u = 0; u < 8; u++)
                    mma_f16(acc[t][u], a0, a1, a2, a3, bf[u][0], bf[u][1]);
            }
        }

        if (kt + 2 < nkt) {
            __syncthreads();
            FILL_STAGE((kt + 2) % 3, (kt + 2) * 32);
            CP_WAIT(1);
            __syncthreads();
        } else if (kt + 1 < nkt) {
            CP_WAIT(0);
            __syncthreads();
        }
    }

    // ---- epilogue ----
    if (mode == 2) {
        const int* tle = tlE + a * NTOK;
        const float* wta = wts + a * NTOK;
#pragma unroll
        for (int t = 0; t < 4; t++) {
            int gr0 = mB + wm0 + t * 16 + r;
            int gr1 = gr0 + 8;
            bool k0 = gr0 < cnt;
            bool k1 = gr1 < cnt;
            if (!k0 && !k1) continue;
            long t0 = k0 ? (long)tle[gr0] : 0;
            long t1 = k1 ? (long)tle[gr1] : 0;
            float w0 = k0 ? wta[gr0] : 0.f;
            float w1v = k1 ? wta[gr1] : 0.f;
            float* d0 = accumC + t0 * CDIM;
            float* d1 = accumC + t1 * CDIM;
#pragma unroll
            for (int u = 0; u < 8; u++) {
                int col = nB + wn0 + u * 8 + c * 2;
                if (k0) {
                    atomicAdd(d0 + col,     acc[t][u][0] * w0);
                    atomicAdd(d0 + col + 1, acc[t][u][1] * w0);
                }
                if (k1) {
                    atomicAdd(d1 + col,     acc[t][u][2] * w1v);
                    atomicAdd(d1 + col + 1, acc[t][u][3] * w1v);
                }
            }
        }
    } else {
#pragma unroll
        for (int t = 0; t < 4; t++) {
            int gr0 = mB + wm0 + t * 16 + r;
            int gr1 = gr0 + 8;
            bool k0 = gr0 < cnt;
            bool k1 = gr1 < cnt;
            if (!k0 && !k1) continue;
#pragma unroll
            for (int u = 0; u < 8; u++) {
                int col = nB + wn0 + u * 8 + c * 2;
                float b0v = bias[a * CR + col], b1v = bias[a * CR + col + 1];
                float v00 = gelu_exact(acc[t][u][0] + b0v);
                float v01 = gelu_exact(acc[t][u][1] + b1v);
                float v10 = gelu_exact(acc[t][u][2] + b0v);
                float v11 = gelu_exact(acc[t][u][3] + b1v);
                if (k0) *(__half2*)(C + (long)gr0 * ldc + col) =
                    __halves2half2(__float2half_rn(v00), __float2half_rn(v01));
                if (k1) *(__half2*)(C + (long)gr1 * ldc + col) =
                    __halves2half2(__float2half_rn(v10), __float2half_rn(v11));
            }
        }
    }
#undef FILL_STAGE
}

// ---------------- final: out = accum + feat, NCHW ----------------
__global__ void final_kernel(const float* __restrict__ feat, float* __restrict__ out) {
    __shared__ float t[32][33];
    int b  = blockIdx.z;
    int c0 = blockIdx.y * 32;
    int p0 = blockIdx.x * 32;
    int tx = threadIdx.x, ty = threadIdx.y;
#pragma unroll
    for (int pj = 0; pj < 4; pj++) {
        int pi = ty + pj * 8;
        long tok = (long)b * HWSZ + p0 + pi;
        t[pi][tx] = g_accum[tok * CDIM + c0 + tx];
    }
    __syncthreads();
    int tid = ty * 32 + tx;
    int pi  = tid & 31;
    int ci0 = tid >> 5;
#pragma unroll
    for (int cj = 0; cj < 4; cj++) {
        int ci = ci0 + cj * 8;
        long off = (long)(b * CDIM + c0 + ci) * HWSZ + p0 + pi;
        out[off] = t[pi][ci] + feat[off];
    }
}

// ---------------- launch ----------------
extern "C" void kernel_launch(void* const* d_in, const int* in_sizes, int n_in,
                              void* d_out, int out_size) {
    const float* feat     = (const float*)d_in[0];
    const float* ar       = (const float*)d_in[1];
    const float* ln_scale = (const float*)d_in[2];
    const float* ln_bias  = (const float*)d_in[3];
    const float* w1       = (const float*)d_in[4];
    const float* w2       = (const float*)d_in[5];
    float* out = (float*)d_out;

    __half *norm, *w1t, *w2t, *h;
    float *bias1, *accum, *wt;
    int *toklist, *cntp;
    cudaGetSymbolAddress((void**)&norm,    g_norm);
    cudaGetSymbolAddress((void**)&w1t,     g_w1t);
    cudaGetSymbolAddress((void**)&w2t,     g_w2t);
    cudaGetSymbolAddress((void**)&bias1,   g_bias1);
    cudaGetSymbolAddress((void**)&h,       g_h);
    cudaGetSymbolAddress((void**)&accum,   g_accum);
    cudaGetSymbolAddress((void**)&toklist, g_toklist);
    cudaGetSymbolAddress((void**)&wt,      g_wt);
    cudaGetSymbolAddress((void**)&cntp,    g_cnt);

    static bool attr_set = false;
    if (!attr_set) {
        cudaFuncSetAttribute(mma_gemm, cudaFuncAttributeMaxDynamicSharedMemorySize, G_SMEM_TOTAL);
        attr_set = true;
    }

    cudaMemsetAsync(accum, 0, (long)NTOK * CDIM * sizeof(float));
    cudaMemsetAsync(cntp,  0, NADP * sizeof(int));
    cudaMemsetAsync(bias1, 0, NADP * CR * sizeof(float));

    compact_kernel<<<NTOK / 256, 256>>>(ar);
    prep_w1_kernel<<<dim3(CDIM / 32, CR / 32, NADP), dim3(32, 8)>>>(ln_scale, ln_bias, w1);
    prep_w2_kernel<<<dim3(CDIM / 32, CR / 32, NADP), dim3(32, 8)>>>(w2);
    ln_stats_kernel<<<dim3(HWSZ / 32, BBAT), dim3(32, 8)>>>(feat);
    ln_apply_kernel<<<dim3(HWSZ / 32, CDIM / 32, BBAT), dim3(32, 8)>>>(feat);

    // GEMM1 (mode 1): h[a][slot] = gelu(norm[tok(slot)] @ w1t[a]^T + bias1[a])
    mma_gemm<<<dim3(NTOK / 128, CR / 128, NADP), 128, G_SMEM_TOTAL>>>(
        norm, w1t, bias1, h, toklist, nullptr, nullptr, nullptr,
        CDIM, CDIM, CDIM, CR,
        0L, (long)CR * CDIM, (long)NTOK * CR, 1);

    // GEMM2 (mode 2): accum[tok] += w * (h[a][slot] @ w2t[a]^T)
    mma_gemm<<<dim3(NTOK / 128, CDIM / 128, NADP), 128, G_SMEM_TOTAL>>>(
        h, w2t, nullptr, nullptr, nullptr, toklist, wt, accum,
        CR, CR, CR, CDIM,
        (long)NTOK * CR, (long)CDIM * CR, 0L, 2);

    // final: out = accum + feat (NCHW)
    final_kernel<<<dim3(HWSZ / 32, CDIM / 32, BBAT), dim3(32, 8)>>>(feat, out);
}

// round 14
// speedup vs baseline: 1.0542x; 1.0293x over previous
#include <cuda_runtime.h>
#include <cuda_fp16.h>
#include <cstdint>
#include <math.h>

#define NTOK 8192
#define CDIM 1024
#define CR   256
#define NADP 10
#define HWSZ 4096
#define BBAT 2
#define NANCH 3

// ---------------- scratch ----------------
static __device__ __half g_norm[(long)NTOK * CDIM];
static __device__ __half g_w1t[(long)NADP * CR * CDIM];
static __device__ __half g_w2t[(long)NADP * CDIM * CR];
static __device__ float  g_bias1[NADP * CR];
static __device__ __half g_h[(long)NADP * NTOK * CR];
static __device__ float  g_accum[(long)NTOK * CDIM];
static __device__ int    g_cnt[NADP];
static __device__ int    g_toklist[NADP * NTOK];
static __device__ float  g_wt[NADP * NTOK];
static __device__ float  g_psum[4][NTOK];
static __device__ float  g_psq[4][NTOK];

// ---------------- helpers ----------------
__device__ __forceinline__ void mma_f16(float* d, uint32_t a0, uint32_t a1, uint32_t a2, uint32_t a3,
                                        uint32_t b0, uint32_t b1) {
    asm volatile("mma.sync.aligned.m16n8k16.row.col.f32.f16.f16.f32 "
        "{%0,%1,%2,%3}, {%4,%5,%6,%7}, {%8,%9}, {%0,%1,%2,%3};"
        : "+f"(d[0]), "+f"(d[1]), "+f"(d[2]), "+f"(d[3])
        : "r"(a0), "r"(a1), "r"(a2), "r"(a3), "r"(b0), "r"(b1));
}
__device__ __forceinline__ void cp16(uint32_t dst, const void* src) {
    asm volatile("cp.async.cg.shared.global [%0], [%1], 16;" :: "r"(dst), "l"(src));
}
#define CP_COMMIT() asm volatile("cp.async.commit_group;" ::: "memory")
#define CP_WAIT(n)  asm volatile("cp.async.wait_group %0;" :: "n"(n) : "memory")
__device__ __forceinline__ uint32_t smem_u32(const void* p) {
    uint32_t a;
    asm("{ .reg .u64 t; cvta.to.shared.u64 t, %1; cvt.u32.u64 %0, t; }" : "=r"(a) : "l"(p));
    return a;
}
__device__ __forceinline__ float gelu_exact(float x) {
    return 0.5f * x * (1.0f + erff(x * 0.70710678118654752440f));
}
__device__ __forceinline__ int adapter_idx(float v) {
    int idx = 0;
    idx += v > (1.0f / 9.0f);
    idx += v > (1.0f / 7.0f);
    idx += v > (1.0f / 5.0f);
    idx += v > (1.0f / 3.0f);
    idx += v > 1.0f;
    idx += v > 3.0f;
    idx += v > 5.0f;
    idx += v > 7.0f;
    idx += v > 9.0f;
    return idx;
}
__device__ __forceinline__ uint32_t lds_u32(const char* base, int row, int ch, int c) {
    return *(const uint32_t*)(base + row * 64 + ((ch ^ ((row >> 1) & 3)) << 4) + c * 4);
}

// ---------------- compaction (+ per-slot weights) ----------------
__global__ void compact_kernel(const float* __restrict__ ar) {
    int tok = blockIdx.x * 256 + threadIdx.x;
    if (tok >= NTOK) return;
    int b = tok >> 12, p = tok & (HWSZ - 1);
    int ids[NANCH];
#pragma unroll
    for (int na = 0; na < NANCH; na++)
        ids[na] = adapter_idx(ar[(long)(b * NANCH + na) * HWSZ + p]);
#pragma unroll
    for (int na = 0; na < NANCH; na++) {
        bool dup = false;
#pragma unroll
        for (int j = 0; j < NANCH; j++) if (j < na) dup |= (ids[j] == ids[na]);
        if (!dup) {
            int occ = 0;
#pragma unroll
            for (int j = 0; j < NANCH; j++) occ += (ids[j] == ids[na]);
            int a = ids[na];
            int s = atomicAdd(&g_cnt[a], 1);
            g_toklist[a * NTOK + s] = tok;
            g_wt[a * NTOK + s] = (float)occ * (1.0f / 3.0f);
        }
    }
}

// ---------------- weight prep (w1 scale-fold + transpose + bias1 fold) ----------------
__global__ void prep_w1_kernel(const float* __restrict__ ln_scale,
                               const float* __restrict__ ln_bias,
                               const float* __restrict__ w1) {
    __shared__ float t[32][33];
    __shared__ float bsum[8][33];
    int a = blockIdx.z, c0 = blockIdx.x * 32, d0 = blockIdx.y * 32;
    int tx = threadIdx.x, ty = threadIdx.y;
    float partial = 0.f;
#pragma unroll
    for (int jj = 0; jj < 4; jj++) {
        int ci = ty + jj * 8;
        float raw = w1[((long)a * CDIM + c0 + ci) * CR + d0 + tx];
        t[ci][tx] = raw * ln_scale[a * CDIM + c0 + ci];
        partial = fmaf(ln_bias[a * CDIM + c0 + ci], raw, partial);
    }
    bsum[ty][tx] = partial;
    __syncthreads();
#pragma unroll
    for (int jj = 0; jj < 4; jj++) {
        int di = ty + jj * 8;
        g_w1t[((long)a * CR + d0 + di) * CDIM + c0 + tx] = __float2half_rn(t[tx][di]);
    }
    if (ty == 0) {
        float s = 0.f;
#pragma unroll
        for (int j = 0; j < 8; j++) s += bsum[j][tx];
        atomicAdd(&g_bias1[a * CR + d0 + tx], s);
    }
}
__global__ void prep_w2_kernel(const float* __restrict__ w2) {
    __shared__ float t[32][33];
    int a = blockIdx.z, n0 = blockIdx.x * 32, k0 = blockIdx.y * 32;
    int tx = threadIdx.x, ty = threadIdx.y;
#pragma unroll
    for (int jj = 0; jj < 4; jj++) {
        int ki = ty + jj * 8;
        t[ki][tx] = w2[((long)a * CR + k0 + ki) * CDIM + n0 + tx];
    }
    __syncthreads();
#pragma unroll
    for (int jj = 0; jj < 4; jj++) {
        int ni = ty + jj * 8;
        g_w2t[((long)a * CDIM + n0 + ni) * CR + k0 + tx] = __float2half_rn(t[tx][ni]);
    }
}

// ---------------- LayerNorm pass 1: partial stats, channel-split 4 ways ----------------
// grid (HWSZ/32, B, 4); block (32,8). Chunk z covers channels [z*256, z*256+256).
__global__ void ln_stats_kernel(const float* __restrict__ feat) {
    int b  = blockIdx.y;
    int p0 = blockIdx.x * 32;
    int zc = blockIdx.z;
    int tx = threadIdx.x, ty = threadIdx.y;
    const float* base = feat + ((long)b * CDIM + zc * 256) * HWSZ + p0 + tx;
    float s = 0.f, sq = 0.f;
#pragma unroll 8
    for (int c = ty; c < 256; c += 8) {
        float v = base[(long)c * HWSZ];
        s += v; sq = fmaf(v, v, sq);
    }
    __shared__ float ss[8][33], qq[8][33];
    ss[ty][tx] = s; qq[ty][tx] = sq;
    __syncthreads();
    if (ty == 0) {
        float S = 0.f, Q = 0.f;
#pragma unroll
        for (int j = 0; j < 8; j++) { S += ss[j][tx]; Q += qq[j][tx]; }
        int tok = b * HWSZ + p0 + tx;
        g_psum[zc][tok] = S;
        g_psq[zc][tok]  = Q;
    }
}

// ---------------- LayerNorm pass 2: combine partials + normalize + transpose ----------------
__global__ void ln_apply_kernel(const float* __restrict__ feat) {
    __shared__ float t[32][33];
    __shared__ float sm_mean[32], sm_rstd[32];
    int b  = blockIdx.z;
    int c0 = blockIdx.y * 32;
    int p0 = blockIdx.x * 32;
    int tx = threadIdx.x, ty = threadIdx.y;
    if (ty == 0) {
        int tok = b * HWSZ + p0 + tx;
        float S = g_psum[0][tok] + g_psum[1][tok] + g_psum[2][tok] + g_psum[3][tok];
        float Q = g_psq[0][tok]  + g_psq[1][tok]  + g_psq[2][tok]  + g_psq[3][tok];
        float mean = S * (1.0f / CDIM);
        float var  = Q * (1.0f / CDIM) - mean * mean;
        sm_mean[tx] = mean;
        sm_rstd[tx] = rsqrtf(var + 1e-5f);
    }
#pragma unroll
    for (int cj = 0; cj < 4; cj++) {
        int ci = ty + cj * 8;
        t[ci][tx] = feat[((long)b * CDIM + c0 + ci) * HWSZ + p0 + tx];
    }
    __syncthreads();
#pragma unroll
    for (int pj = 0; pj < 4; pj++) {
        int pi = ty + pj * 8;
        long tok = (long)b * HWSZ + p0 + pi;
        float mean = sm_mean[pi], rstd = sm_rstd[pi];
        g_norm[tok * CDIM + c0 + tx] = __float2half_rn((t[tx][pi] - mean) * rstd);
    }
}

// ---------------- fp16 mma.sync GEMM: 128x128 CTA, 4 warps of 64x64, cp.async 3-stage ----------------
#define G_STAGES   3
#define G_STAGE_B  16384
#define G_PTRS_B   2048
#define G_SMEM_TOTAL (G_PTRS_B + G_STAGES * G_STAGE_B)

__global__ void __launch_bounds__(128, 2)
mma_gemm(const __half* __restrict__ Ab, const __half* __restrict__ Bb,
         const float* __restrict__ bias, __half* __restrict__ Cb,
         const int* __restrict__ tlA,
         const int* __restrict__ tlE,
         const float* __restrict__ wts,
         float* __restrict__ accumC,
         int K, int lda, int ldb, int ldc,
         long sA, long sB, long sC, int mode)
{
    extern __shared__ char smem[];
    int tid = threadIdx.x;
    int mB = blockIdx.x * 128, nB = blockIdx.y * 128, a = blockIdx.z;

    int cnt = g_cnt[a];
    if (mB >= cnt) return;

    const __half* A = Ab + (long)a * sA;
    const __half* B = Bb + (long)a * sB;
    __half* C = Cb + (long)a * sC;
    const int* tla = tlA ? tlA + a * NTOK : nullptr;

    const __half** sAp = (const __half**)smem;
    const __half** sBp = sAp + 128;
    uint32_t sm_base = smem_u32(smem) + G_PTRS_B;

    {
        int m = mB + tid;
        int mc = m < cnt ? m : (cnt - 1);
        long arow = tla ? (long)tla[mc] : (long)mc;
        sAp[tid] = A + arow * lda;
        sBp[tid] = B + (long)(nB + tid) * ldb;
    }
    __syncthreads();

    int lane = tid & 31, wid = tid >> 5;
    int wm0 = (wid & 1) * 64;
    int wn0 = (wid >> 1) * 64;
    int r = lane >> 2, c = lane & 3;

    int nkt = K >> 5;
    int kc = tid & 3;
    int r0 = tid >> 2;

#define FILL_STAGE(sidx, k0)  do {                                             \
        uint32_t base = sm_base + (sidx) * G_STAGE_B;                          \
        _Pragma("unroll")                                                      \
        for (int i = 0; i < 4; i++) {                                          \
            int row = r0 + i * 32;                                             \
            uint32_t off = (uint32_t)(row * 64 + ((kc ^ ((row >> 1) & 3)) << 4)); \
            cp16(base + off, sAp[row] + (k0) + kc * 8);                        \
            cp16(base + 8192 + off, sBp[row] + (k0) + kc * 8);                 \
        }                                                                      \
        CP_COMMIT();                                                           \
    } while (0)

    float acc[4][8][4];
#pragma unroll
    for (int t = 0; t < 4; t++)
#pragma unroll
        for (int u = 0; u < 8; u++)
#pragma unroll
            for (int e = 0; e < 4; e++) acc[t][u][e] = 0.f;

    FILL_STAGE(0, 0);
    FILL_STAGE(1, 32);
    CP_WAIT(1);
    __syncthreads();

    for (int kt = 0; kt < nkt; kt++) {
        const char* As = smem + G_PTRS_B + (kt % 3) * G_STAGE_B;
        const char* Bs = As + 8192;

#pragma unroll
        for (int j = 0; j < 2; j++) {
            uint32_t bf[8][2];
#pragma unroll
            for (int u = 0; u < 8; u++) {
                int n = wn0 + u * 8 + r;
                bf[u][0] = lds_u32(Bs, n, 2 * j,     c);
                bf[u][1] = lds_u32(Bs, n, 2 * j + 1, c);
            }
#pragma unroll
            for (int t = 0; t < 4; t++) {
                int m0 = wm0 + t * 16 + r;
                uint32_t a0 = lds_u32(As, m0,     2 * j,     c);
                uint32_t a1 = lds_u32(As, m0 + 8, 2 * j,     c);
                uint32_t a2 = lds_u32(As, m0,     2 * j + 1, c);
                uint32_t a3 = lds_u32(As, m0 + 8, 2 * j + 1, c);
#pragma unroll
                for (int u = 0; u < 8; u++)
                    mma_f16(acc[t][u], a0, a1, a2, a3, bf[u][0], bf[u][1]);
            }
        }

        if (kt + 2 < nkt) {
            __syncthreads();
            FILL_STAGE((kt + 2) % 3, (kt + 2) * 32);
            CP_WAIT(1);
            __syncthreads();
        } else if (kt + 1 < nkt) {
            CP_WAIT(0);
            __syncthreads();
        }
    }

    // ---- epilogue ----
    if (mode == 2) {
        const int* tle = tlE + a * NTOK;
        const float* wta = wts + a * NTOK;
#pragma unroll
        for (int t = 0; t < 4; t++) {
            int gr0 = mB + wm0 + t * 16 + r;
            int gr1 = gr0 + 8;
            bool k0 = gr0 < cnt;
            bool k1 = gr1 < cnt;
            if (!k0 && !k1) continue;
            long t0 = k0 ? (long)tle[gr0] : 0;
            long t1 = k1 ? (long)tle[gr1] : 0;
            float w0 = k0 ? wta[gr0] : 0.f;
            float w1v = k1 ? wta[gr1] : 0.f;
            float* d0 = accumC + t0 * CDIM;
            float* d1 = accumC + t1 * CDIM;
#pragma unroll
            for (int u = 0; u < 8; u++) {
                int col = nB + wn0 + u * 8 + c * 2;
                if (k0) {
                    atomicAdd(d0 + col,     acc[t][u][0] * w0);
                    atomicAdd(d0 + col + 1, acc[t][u][1] * w0);
                }
                if (k1) {
                    atomicAdd(d1 + col,     acc[t][u][2] * w1v);
                    atomicAdd(d1 + col + 1, acc[t][u][3] * w1v);
                }
            }
        }
    } else {
#pragma unroll
        for (int t = 0; t < 4; t++) {
            int gr0 = mB + wm0 + t * 16 + r;
            int gr1 = gr0 + 8;
            bool k0 = gr0 < cnt;
            bool k1 = gr1 < cnt;
            if (!k0 && !k1) continue;
#pragma unroll
            for (int u = 0; u < 8; u++) {
                int col = nB + wn0 + u * 8 + c * 2;
                float b0v = bias[a * CR + col], b1v = bias[a * CR + col + 1];
                float v00 = gelu_exact(acc[t][u][0] + b0v);
                float v01 = gelu_exact(acc[t][u][1] + b1v);
                float v10 = gelu_exact(acc[t][u][2] + b0v);
                float v11 = gelu_exact(acc[t][u][3] + b1v);
                if (k0) *(__half2*)(C + (long)gr0 * ldc + col) =
                    __halves2half2(__float2half_rn(v00), __float2half_rn(v01));
                if (k1) *(__half2*)(C + (long)gr1 * ldc + col) =
                    __halves2half2(__float2half_rn(v10), __float2half_rn(v11));
            }
        }
    }
#undef FILL_STAGE
}

// ---------------- final: out = accum + feat, NCHW ----------------
__global__ void final_kernel(const float* __restrict__ feat, float* __restrict__ out) {
    __shared__ float t[32][33];
    int b  = blockIdx.z;
    int c0 = blockIdx.y * 32;
    int p0 = blockIdx.x * 32;
    int tx = threadIdx.x, ty = threadIdx.y;
#pragma unroll
    for (int pj = 0; pj < 4; pj++) {
        int pi = ty + pj * 8;
        long tok = (long)b * HWSZ + p0 + pi;
        t[pi][tx] = g_accum[tok * CDIM + c0 + tx];
    }
    __syncthreads();
    int tid = ty * 32 + tx;
    int pi  = tid & 31;
    int ci0 = tid >> 5;
#pragma unroll
    for (int cj = 0; cj < 4; cj++) {
        int ci = ci0 + cj * 8;
        long off = (long)(b * CDIM + c0 + ci) * HWSZ + p0 + pi;
        out[off] = t[pi][ci] + feat[off];
    }
}

// ---------------- launch ----------------
extern "C" void kernel_launch(void* const* d_in, const int* in_sizes, int n_in,
                              void* d_out, int out_size) {
    const float* feat     = (const float*)d_in[0];
    const float* ar       = (const float*)d_in[1];
    const float* ln_scale = (const float*)d_in[2];
    const float* ln_bias  = (const float*)d_in[3];
    const float* w1       = (const float*)d_in[4];
    const float* w2       = (const float*)d_in[5];
    float* out = (float*)d_out;

    __half *norm, *w1t, *w2t, *h;
    float *bias1, *accum, *wt;
    int *toklist, *cntp;
    cudaGetSymbolAddress((void**)&norm,    g_norm);
    cudaGetSymbolAddress((void**)&w1t,     g_w1t);
    cudaGetSymbolAddress((void**)&w2t,     g_w2t);
    cudaGetSymbolAddress((void**)&bias1,   g_bias1);
    cudaGetSymbolAddress((void**)&h,       g_h);
    cudaGetSymbolAddress((void**)&accum,   g_accum);
    cudaGetSymbolAddress((void**)&toklist, g_toklist);
    cudaGetSymbolAddress((void**)&wt,      g_wt);
    cudaGetSymbolAddress((void**)&cntp,    g_cnt);

    static bool attr_set = false;
    if (!attr_set) {
        cudaFuncSetAttribute(mma_gemm, cudaFuncAttributeMaxDynamicSharedMemorySize, G_SMEM_TOTAL);
        attr_set = true;
    }

    cudaMemsetAsync(accum, 0, (long)NTOK * CDIM * sizeof(float));
    cudaMemsetAsync(cntp,  0, NADP * sizeof(int));
    cudaMemsetAsync(bias1, 0, NADP * CR * sizeof(float));

    compact_kernel<<<NTOK / 256, 256>>>(ar);
    prep_w1_kernel<<<dim3(CDIM / 32, CR / 32, NADP), dim3(32, 8)>>>(ln_scale, ln_bias, w1);
    prep_w2_kernel<<<dim3(CDIM / 32, CR / 32, NADP), dim3(32, 8)>>>(w2);
    ln_stats_kernel<<<dim3(HWSZ / 32, BBAT, 4), dim3(32, 8)>>>(feat);
    ln_apply_kernel<<<dim3(HWSZ / 32, CDIM / 32, BBAT), dim3(32, 8)>>>(feat);

    // GEMM1 (mode 1): h[a][slot] = gelu(norm[tok(slot)] @ w1t[a]^T + bias1[a])
    mma_gemm<<<dim3(NTOK / 128, CR / 128, NADP), 128, G_SMEM_TOTAL>>>(
        norm, w1t, bias1, h, toklist, nullptr, nullptr, nullptr,
        CDIM, CDIM, CDIM, CR,
        0L, (long)CR * CDIM, (long)NTOK * CR, 1);

    // GEMM2 (mode 2): accum[tok] += w * (h[a][slot] @ w2t[a]^T)
    mma_gemm<<<dim3(NTOK / 128, CDIM / 128, NADP), 128, G_SMEM_TOTAL>>>(
        h, w2t, nullptr, nullptr, nullptr, toklist, wt, accum,
        CR, CR, CR, CDIM,
        (long)NTOK * CR, (long)CDIM * CR, 0L, 2);

    // final: out = accum + feat (NCHW)
    final_kernel<<<dim3(HWSZ / 32, CDIM / 32, BBAT), dim3(32, 8)>>>(feat, out);
}

// round 15
// speedup vs baseline: 1.1170x; 1.0595x over previous
#include <cuda_runtime.h>
#include <cuda_fp16.h>
#include <cstdint>
#include <math.h>

#define NTOK 8192
#define CDIM 1024
#define CR   256
#define NADP 10
#define HWSZ 4096
#define BBAT 2
#define NANCH 3

// ---------------- scratch ----------------
static __device__ __half g_norm[(long)NTOK * CDIM];
static __device__ __half g_w1t[(long)NADP * CR * CDIM];
static __device__ __half g_w2t[(long)NADP * CDIM * CR];
static __device__ float  g_bias1[NADP * CR];
static __device__ __half g_h[(long)NADP * NTOK * CR];
static __device__ float  g_accum[(long)NTOK * CDIM];
static __device__ int    g_cnt[NADP];
static __device__ int    g_toklist[NADP * NTOK];
static __device__ float  g_wt[NADP * NTOK];
static __device__ float  g_psum[4][NTOK];
static __device__ float  g_psq[4][NTOK];

// ---------------- helpers ----------------
__device__ __forceinline__ void mma_f16(float* d, uint32_t a0, uint32_t a1, uint32_t a2, uint32_t a3,
                                        uint32_t b0, uint32_t b1) {
    asm volatile("mma.sync.aligned.m16n8k16.row.col.f32.f16.f16.f32 "
        "{%0,%1,%2,%3}, {%4,%5,%6,%7}, {%8,%9}, {%0,%1,%2,%3};"
        : "+f"(d[0]), "+f"(d[1]), "+f"(d[2]), "+f"(d[3])
        : "r"(a0), "r"(a1), "r"(a2), "r"(a3), "r"(b0), "r"(b1));
}
__device__ __forceinline__ void red_add_v2(float* ptr, float v0, float v1) {
    asm volatile("red.global.add.v2.f32 [%0], {%1, %2};"
                 :: "l"(ptr), "f"(v0), "f"(v1) : "memory");
}
__device__ __forceinline__ void cp16(uint32_t dst, const void* src) {
    asm volatile("cp.async.cg.shared.global [%0], [%1], 16;" :: "r"(dst), "l"(src));
}
#define CP_COMMIT() asm volatile("cp.async.commit_group;" ::: "memory")
#define CP_WAIT(n)  asm volatile("cp.async.wait_group %0;" :: "n"(n) : "memory")
__device__ __forceinline__ uint32_t smem_u32(const void* p) {
    uint32_t a;
    asm("{ .reg .u64 t; cvta.to.shared.u64 t, %1; cvt.u32.u64 %0, t; }" : "=r"(a) : "l"(p));
    return a;
}
__device__ __forceinline__ float gelu_exact(float x) {
    return 0.5f * x * (1.0f + erff(x * 0.70710678118654752440f));
}
__device__ __forceinline__ int adapter_idx(float v) {
    int idx = 0;
    idx += v > (1.0f / 9.0f);
    idx += v > (1.0f / 7.0f);
    idx += v > (1.0f / 5.0f);
    idx += v > (1.0f / 3.0f);
    idx += v > 1.0f;
    idx += v > 3.0f;
    idx += v > 5.0f;
    idx += v > 7.0f;
    idx += v > 9.0f;
    return idx;
}
__device__ __forceinline__ uint32_t lds_u32(const char* base, int row, int ch, int c) {
    return *(const uint32_t*)(base + row * 64 + ((ch ^ ((row >> 1) & 3)) << 4) + c * 4);
}

// ---------------- merged weight prep: w1 fold+transpose+bias1, then w2 transpose ----------------
__global__ void prep_w_kernel(const float* __restrict__ ln_scale,
                              const float* __restrict__ ln_bias,
                              const float* __restrict__ w1,
                              const float* __restrict__ w2) {
    __shared__ float t[32][33];
    __shared__ float bsum[8][33];
    int a = blockIdx.z, x0 = blockIdx.x * 32, y0 = blockIdx.y * 32;
    int tx = threadIdx.x, ty = threadIdx.y;

    // --- w1: c0 = x0 (over CDIM), d0 = y0 (over CR) ---
    float partial = 0.f;
#pragma unroll
    for (int jj = 0; jj < 4; jj++) {
        int ci = ty + jj * 8;
        float raw = w1[((long)a * CDIM + x0 + ci) * CR + y0 + tx];
        t[ci][tx] = raw * ln_scale[a * CDIM + x0 + ci];
        partial = fmaf(ln_bias[a * CDIM + x0 + ci], raw, partial);
    }
    bsum[ty][tx] = partial;
    __syncthreads();
#pragma unroll
    for (int jj = 0; jj < 4; jj++) {
        int di = ty + jj * 8;
        g_w1t[((long)a * CR + y0 + di) * CDIM + x0 + tx] = __float2half_rn(t[tx][di]);
    }
    if (ty == 0) {
        float s = 0.f;
#pragma unroll
        for (int j = 0; j < 8; j++) s += bsum[j][tx];
        atomicAdd(&g_bias1[a * CR + y0 + tx], s);
    }
    __syncthreads();

    // --- w2: n0 = x0 (over CDIM), k0 = y0 (over CR) ---
#pragma unroll
    for (int jj = 0; jj < 4; jj++) {
        int ki = ty + jj * 8;
        t[ki][tx] = w2[((long)a * CR + y0 + ki) * CDIM + x0 + tx];
    }
    __syncthreads();
#pragma unroll
    for (int jj = 0; jj < 4; jj++) {
        int ni = ty + jj * 8;
        g_w2t[((long)a * CDIM + x0 + ni) * CR + y0 + tx] = __float2half_rn(t[tx][ni]);
    }
}

// ---------------- LayerNorm pass 1 (+ fused compaction on zc==0) ----------------
// grid (HWSZ/32, B, 4); block (32,8). Chunk z covers channels [z*256, z*256+256).
__global__ void ln_stats_kernel(const float* __restrict__ feat, const float* __restrict__ ar) {
    int b  = blockIdx.y;
    int p0 = blockIdx.x * 32;
    int zc = blockIdx.z;
    int tx = threadIdx.x, ty = threadIdx.y;
    const float* base = feat + ((long)b * CDIM + zc * 256) * HWSZ + p0 + tx;
    float s = 0.f, sq = 0.f;
#pragma unroll 8
    for (int c = ty; c < 256; c += 8) {
        float v = base[(long)c * HWSZ];
        s += v; sq = fmaf(v, v, sq);
    }
    __shared__ float ss[8][33], qq[8][33];
    ss[ty][tx] = s; qq[ty][tx] = sq;
    __syncthreads();
    if (ty == 0) {
        float S = 0.f, Q = 0.f;
#pragma unroll
        for (int j = 0; j < 8; j++) { S += ss[j][tx]; Q += qq[j][tx]; }
        int tok = b * HWSZ + p0 + tx;
        g_psum[zc][tok] = S;
        g_psq[zc][tok]  = Q;
    }
    // fused compaction: one thread per token, on the zc==0 slice
    if (zc == 0 && ty == 1) {
        int p = p0 + tx;
        int tok = b * HWSZ + p;
        int ids[NANCH];
#pragma unroll
        for (int na = 0; na < NANCH; na++)
            ids[na] = adapter_idx(ar[(long)(b * NANCH + na) * HWSZ + p]);
#pragma unroll
        for (int na = 0; na < NANCH; na++) {
            bool dup = false;
#pragma unroll
            for (int j = 0; j < NANCH; j++) if (j < na) dup |= (ids[j] == ids[na]);
            if (!dup) {
                int occ = 0;
#pragma unroll
                for (int j = 0; j < NANCH; j++) occ += (ids[j] == ids[na]);
                int a = ids[na];
                int sl = atomicAdd(&g_cnt[a], 1);
                g_toklist[a * NTOK + sl] = tok;
                g_wt[a * NTOK + sl] = (float)occ * (1.0f / 3.0f);
            }
        }
    }
}

// ---------------- LayerNorm pass 2: combine partials + normalize + transpose ----------------
__global__ void ln_apply_kernel(const float* __restrict__ feat) {
    __shared__ float t[32][33];
    __shared__ float sm_mean[32], sm_rstd[32];
    int b  = blockIdx.z;
    int c0 = blockIdx.y * 32;
    int p0 = blockIdx.x * 32;
    int tx = threadIdx.x, ty = threadIdx.y;
    if (ty == 0) {
        int tok = b * HWSZ + p0 + tx;
        float S = g_psum[0][tok] + g_psum[1][tok] + g_psum[2][tok] + g_psum[3][tok];
        float Q = g_psq[0][tok]  + g_psq[1][tok]  + g_psq[2][tok]  + g_psq[3][tok];
        float mean = S * (1.0f / CDIM);
        float var  = Q * (1.0f / CDIM) - mean * mean;
        sm_mean[tx] = mean;
        sm_rstd[tx] = rsqrtf(var + 1e-5f);
    }
#pragma unroll
    for (int cj = 0; cj < 4; cj++) {
        int ci = ty + cj * 8;
        t[ci][tx] = feat[((long)b * CDIM + c0 + ci) * HWSZ + p0 + tx];
    }
    __syncthreads();
#pragma unroll
    for (int pj = 0; pj < 4; pj++) {
        int pi = ty + pj * 8;
        long tok = (long)b * HWSZ + p0 + pi;
        float mean = sm_mean[pi], rstd = sm_rstd[pi];
        g_norm[tok * CDIM + c0 + tx] = __float2half_rn((t[tx][pi] - mean) * rstd);
    }
}

// ---------------- fp16 mma.sync GEMM: 128x128 CTA, 4 warps of 64x64, cp.async 3-stage ----------------
#define G_STAGES   3
#define G_STAGE_B  16384
#define G_PTRS_B   2048
#define G_SMEM_TOTAL (G_PTRS_B + G_STAGES * G_STAGE_B)

__global__ void __launch_bounds__(128, 2)
mma_gemm(const __half* __restrict__ Ab, const __half* __restrict__ Bb,
         const float* __restrict__ bias, __half* __restrict__ Cb,
         const int* __restrict__ tlA,
         const int* __restrict__ tlE,
         const float* __restrict__ wts,
         float* __restrict__ accumC,
         int K, int lda, int ldb, int ldc,
         long sA, long sB, long sC, int mode)
{
    extern __shared__ char smem[];
    int tid = threadIdx.x;
    int mB = blockIdx.x * 128, nB = blockIdx.y * 128, a = blockIdx.z;

    int cnt = g_cnt[a];
    if (mB >= cnt) return;

    const __half* A = Ab + (long)a * sA;
    const __half* B = Bb + (long)a * sB;
    __half* C = Cb + (long)a * sC;
    const int* tla = tlA ? tlA + a * NTOK : nullptr;

    const __half** sAp = (const __half**)smem;
    const __half** sBp = sAp + 128;
    uint32_t sm_base = smem_u32(smem) + G_PTRS_B;

    {
        int m = mB + tid;
        int mc = m < cnt ? m : (cnt - 1);
        long arow = tla ? (long)tla[mc] : (long)mc;
        sAp[tid] = A + arow * lda;
        sBp[tid] = B + (long)(nB + tid) * ldb;
    }
    __syncthreads();

    int lane = tid & 31, wid = tid >> 5;
    int wm0 = (wid & 1) * 64;
    int wn0 = (wid >> 1) * 64;
    int r = lane >> 2, c = lane & 3;

    int nkt = K >> 5;
    int kc = tid & 3;
    int r0 = tid >> 2;

#define FILL_STAGE(sidx, k0)  do {                                             \
        uint32_t base = sm_base + (sidx) * G_STAGE_B;                          \
        _Pragma("unroll")                                                      \
        for (int i = 0; i < 4; i++) {                                          \
            int row = r0 + i * 32;                                             \
            uint32_t off = (uint32_t)(row * 64 + ((kc ^ ((row >> 1) & 3)) << 4)); \
            cp16(base + off, sAp[row] + (k0) + kc * 8);                        \
            cp16(base + 8192 + off, sBp[row] + (k0) + kc * 8);                 \
        }                                                                      \
        CP_COMMIT();                                                           \
    } while (0)

    float acc[4][8][4];
#pragma unroll
    for (int t = 0; t < 4; t++)
#pragma unroll
        for (int u = 0; u < 8; u++)
#pragma unroll
            for (int e = 0; e < 4; e++) acc[t][u][e] = 0.f;

    FILL_STAGE(0, 0);
    FILL_STAGE(1, 32);
    CP_WAIT(1);
    __syncthreads();

    for (int kt = 0; kt < nkt; kt++) {
        const char* As = smem + G_PTRS_B + (kt % 3) * G_STAGE_B;
        const char* Bs = As + 8192;

#pragma unroll
        for (int j = 0; j < 2; j++) {
            uint32_t bf[8][2];
#pragma unroll
            for (int u = 0; u < 8; u++) {
                int n = wn0 + u * 8 + r;
                bf[u][0] = lds_u32(Bs, n, 2 * j,     c);
                bf[u][1] = lds_u32(Bs, n, 2 * j + 1, c);
            }
#pragma unroll
            for (int t = 0; t < 4; t++) {
                int m0 = wm0 + t * 16 + r;
                uint32_t a0 = lds_u32(As, m0,     2 * j,     c);
                uint32_t a1 = lds_u32(As, m0 + 8, 2 * j,     c);
                uint32_t a2 = lds_u32(As, m0,     2 * j + 1, c);
                uint32_t a3 = lds_u32(As, m0 + 8, 2 * j + 1, c);
#pragma unroll
                for (int u = 0; u < 8; u++)
                    mma_f16(acc[t][u], a0, a1, a2, a3, bf[u][0], bf[u][1]);
            }
        }

        if (kt + 2 < nkt) {
            __syncthreads();
            FILL_STAGE((kt + 2) % 3, (kt + 2) * 32);
            CP_WAIT(1);
            __syncthreads();
        } else if (kt + 1 < nkt) {
            CP_WAIT(0);
            __syncthreads();
        }
    }

    // ---- epilogue ----
    if (mode == 2) {
        const int* tle = tlE + a * NTOK;
        const float* wta = wts + a * NTOK;
#pragma unroll
        for (int t = 0; t < 4; t++) {
            int gr0 = mB + wm0 + t * 16 + r;
            int gr1 = gr0 + 8;
            bool k0 = gr0 < cnt;
            bool k1 = gr1 < cnt;
            if (!k0 && !k1) continue;
            long t0 = k0 ? (long)tle[gr0] : 0;
            long t1 = k1 ? (long)tle[gr1] : 0;
            float w0 = k0 ? wta[gr0] : 0.f;
            float w1v = k1 ? wta[gr1] : 0.f;
            float* d0 = accumC + t0 * CDIM;
            float* d1 = accumC + t1 * CDIM;
#pragma unroll
            for (int u = 0; u < 8; u++) {
                int col = nB + wn0 + u * 8 + c * 2;
                if (k0) red_add_v2(d0 + col, acc[t][u][0] * w0,  acc[t][u][1] * w0);
                if (k1) red_add_v2(d1 + col, acc[t][u][2] * w1v, acc[t][u][3] * w1v);
            }
        }
    } else {
#pragma unroll
        for (int t = 0; t < 4; t++) {
            int gr0 = mB + wm0 + t * 16 + r;
            int gr1 = gr0 + 8;
            bool k0 = gr0 < cnt;
            bool k1 = gr1 < cnt;
            if (!k0 && !k1) continue;
#pragma unroll
            for (int u = 0; u < 8; u++) {
                int col = nB + wn0 + u * 8 + c * 2;
                float b0v = bias[a * CR + col], b1v = bias[a * CR + col + 1];
                float v00 = gelu_exact(acc[t][u][0] + b0v);
                float v01 = gelu_exact(acc[t][u][1] + b1v);
                float v10 = gelu_exact(acc[t][u][2] + b0v);
                float v11 = gelu_exact(acc[t][u][3] + b1v);
                if (k0) *(__half2*)(C + (long)gr0 * ldc + col) =
                    __halves2half2(__float2half_rn(v00), __float2half_rn(v01));
                if (k1) *(__half2*)(C + (long)gr1 * ldc + col) =
                    __halves2half2(__float2half_rn(v10), __float2half_rn(v11));
            }
        }
    }
#undef FILL_STAGE
}

// ---------------- final: out = accum + feat, NCHW ----------------
__global__ void final_kernel(const float* __restrict__ feat, float* __restrict__ out) {
    __shared__ float t[32][33];
    int b  = blockIdx.z;
    int c0 = blockIdx.y * 32;
    int p0 = blockIdx.x * 32;
    int tx = threadIdx.x, ty = threadIdx.y;
#pragma unroll
    for (int pj = 0; pj < 4; pj++) {
        int pi = ty + pj * 8;
        long tok = (long)b * HWSZ + p0 + pi;
        t[pi][tx] = g_accum[tok * CDIM + c0 + tx];
    }
    __syncthreads();
    int tid = ty * 32 + tx;
    int pi  = tid & 31;
    int ci0 = tid >> 5;
#pragma unroll
    for (int cj = 0; cj < 4; cj++) {
        int ci = ci0 + cj * 8;
        long off = (long)(b * CDIM + c0 + ci) * HWSZ + p0 + pi;
        out[off] = t[pi][ci] + feat[off];
    }
}

// ---------------- launch ----------------
extern "C" void kernel_launch(void* const* d_in, const int* in_sizes, int n_in,
                              void* d_out, int out_size) {
    const float* feat     = (const float*)d_in[0];
    const float* ar       = (const float*)d_in[1];
    const float* ln_scale = (const float*)d_in[2];
    const float* ln_bias  = (const float*)d_in[3];
    const float* w1       = (const float*)d_in[4];
    const float* w2       = (const float*)d_in[5];
    float* out = (float*)d_out;

    __half *norm, *w1t, *w2t, *h;
    float *bias1, *accum, *wt;
    int *toklist, *cntp;
    cudaGetSymbolAddress((void**)&norm,    g_norm);
    cudaGetSymbolAddress((void**)&w1t,     g_w1t);
    cudaGetSymbolAddress((void**)&w2t,     g_w2t);
    cudaGetSymbolAddress((void**)&bias1,   g_bias1);
    cudaGetSymbolAddress((void**)&h,       g_h);
    cudaGetSymbolAddress((void**)&accum,   g_accum);
    cudaGetSymbolAddress((void**)&toklist, g_toklist);
    cudaGetSymbolAddress((void**)&wt,      g_wt);
    cudaGetSymbolAddress((void**)&cntp,    g_cnt);

    static bool attr_set = false;
    if (!attr_set) {
        cudaFuncSetAttribute(mma_gemm, cudaFuncAttributeMaxDynamicSharedMemorySize, G_SMEM_TOTAL);
        attr_set = true;
    }

    cudaMemsetAsync(accum, 0, (long)NTOK * CDIM * sizeof(float));
    cudaMemsetAsync(cntp,  0, NADP * sizeof(int));
    cudaMemsetAsync(bias1, 0, NADP * CR * sizeof(float));

    prep_w_kernel<<<dim3(CDIM / 32, CR / 32, NADP), dim3(32, 8)>>>(ln_scale, ln_bias, w1, w2);
    ln_stats_kernel<<<dim3(HWSZ / 32, BBAT, 4), dim3(32, 8)>>>(feat, ar);
    ln_apply_kernel<<<dim3(HWSZ / 32, CDIM / 32, BBAT), dim3(32, 8)>>>(feat);

    // GEMM1 (mode 1): h[a][slot] = gelu(norm[tok(slot)] @ w1t[a]^T + bias1[a])
    mma_gemm<<<dim3(NTOK / 128, CR / 128, NADP), 128, G_SMEM_TOTAL>>>(
        norm, w1t, bias1, h, toklist, nullptr, nullptr, nullptr,
        CDIM, CDIM, CDIM, CR,
        0L, (long)CR * CDIM, (long)NTOK * CR, 1);

    // GEMM2 (mode 2): accum[tok] += w * (h[a][slot] @ w2t[a]^T)
    mma_gemm<<<dim3(NTOK / 128, CDIM / 128, NADP), 128, G_SMEM_TOTAL>>>(
        h, w2t, nullptr, nullptr, nullptr, toklist, wt, accum,
        CR, CR, CR, CDIM,
        (long)NTOK * CR, (long)CDIM * CR, 0L, 2);

    // final: out = accum + feat (NCHW)
    final_kernel<<<dim3(HWSZ / 32, CDIM / 32, BBAT), dim3(32, 8)>>>(feat, out);
}